// round 17
// baseline (speedup 1.0000x reference)
#include <cuda_runtime.h>
#include <cuda_fp16.h>
#include <math.h>
#include <stdint.h>

#define DIM   768
#define HEADS 12
#define HD    64
#define B_    2
#define WW    48
#define NTOK  2304
#define BHC   24
#define MROWS 4608

// -------- scratch (device globals; no allocation allowed) --------
__device__ __half g_qh[BHC*NTOK*HD];          // Q: fp16 (pre-scaled)
__device__ __half g_kh[BHC*NTOK*HD];          // K: fp16
__device__ __half g_vh[BHC*NTOK*HD];          // V: fp16
__device__ __half g_x16[MROWS*DIM];           // x fp16
__device__ __half g_wq16[3*DIM*DIM];          // w_qkv fp16
__device__ __half g_wp16[DIM*DIM];            // w_proj fp16
__device__ __half g_o16[MROWS*DIM];           // O fp16
__device__ float g_sin[NTOK*32], g_cos[NTOK*32];

// ==================== helpers ====================
__device__ __forceinline__ uint32_t smem_u32(const void* p) {
    uint32_t a;
    asm("{ .reg .u64 t; cvta.to.shared.u64 t, %1; cvt.u32.u64 %0, t; }" : "=r"(a) : "l"(p));
    return a;
}
__device__ __forceinline__ void ldsm4(uint32_t* r, uint32_t addr) {
    asm volatile("ldmatrix.sync.aligned.m8n8.x4.shared.b16 {%0,%1,%2,%3}, [%4];"
                 : "=r"(r[0]), "=r"(r[1]), "=r"(r[2]), "=r"(r[3]) : "r"(addr));
}
__device__ __forceinline__ void ldsm4t(uint32_t* r, uint32_t addr) {
    asm volatile("ldmatrix.sync.aligned.m8n8.x4.trans.shared.b16 {%0,%1,%2,%3}, [%4];"
                 : "=r"(r[0]), "=r"(r[1]), "=r"(r[2]), "=r"(r[3]) : "r"(addr));
}
__device__ __forceinline__ void mma_fp(float* d, const uint32_t* a,
                                       uint32_t b0, uint32_t b1) {
    asm volatile(
        "mma.sync.aligned.m16n8k16.row.col.f32.f16.f16.f32 "
        "{%0,%1,%2,%3}, {%4,%5,%6,%7}, {%8,%9}, {%0,%1,%2,%3};"
        : "+f"(d[0]), "+f"(d[1]), "+f"(d[2]), "+f"(d[3])
        : "r"(a[0]), "r"(a[1]), "r"(a[2]), "r"(a[3]), "r"(b0), "r"(b1));
}
// e^x via MUFU (ex2.approx): runs on the otherwise-idle MUFU pipe.
__device__ __forceinline__ float fast_exp(float x) {
    float r;
    asm("ex2.approx.f32 %0, %1;" : "=f"(r) : "f"(x * 1.4426950409f));
    return r;
}

// ==================== fused prep kernel (converts + rope table) =========
#define N4_X  (MROWS*DIM/4)
#define N4_WQ (3*DIM*DIM/4)
#define N4_WP (DIM*DIM/4)
#define N_ROPE (NTOK*32)
#define PREP_TOTAL (N4_X + N4_WQ + N4_WP + N_ROPE)

__global__ void __launch_bounds__(256) prep_kernel(
    const float* __restrict__ x, const float* __restrict__ wq,
    const float* __restrict__ wp)
{
    int idx = blockIdx.x * 256 + threadIdx.x;
    if (idx < N4_X + N4_WQ + N4_WP) {
        const float* src;
        __half* dst;
        int i;
        if (idx < N4_X)                { src = x;  dst = g_x16;  i = idx; }
        else if (idx < N4_X + N4_WQ)   { src = wq; dst = g_wq16; i = idx - N4_X; }
        else                           { src = wp; dst = g_wp16; i = idx - N4_X - N4_WQ; }
        float4 v = ((const float4*)src)[i];
        ((__half2*)dst)[2*i]   = __floats2half2_rn(v.x, v.y);
        ((__half2*)dst)[2*i+1] = __floats2half2_rn(v.z, v.w);
        return;
    }
    int r = idx - (N4_X + N4_WQ + N4_WP);
    if (r >= N_ROPE) return;
    int n = r >> 5, j = r & 31;
    int axis = j >> 4, p = j & 15;
    int y = n / WW, xx = n - y * WW;
    float idxf  = axis ? (float)xx : (float)y;
    float coord = 2.0f * ((idxf + 0.5f) / 48.0f) - 1.0f;
    float invp  = exp2f(-(float)p * 0.41524101186092607f);  // 100^(-p/16)
    float sn, cs; sincosf(6.283185307179586f * coord * invp, &sn, &cs);
    g_sin[r] = sn; g_cos[r] = cs;
}

// ==================== mma.sync fp16 GEMM (plain fp16, fp32 accum) ======
#define TSTRIDE 40
#define TILE_B  (128*TSTRIDE*2)       // 10240 bytes per tile
#define STAGE_B (2*TILE_B)            // A | B
#define GEMM_SMEM_B (2*STAGE_B)       // 40960 bytes

__device__ __forceinline__ void g2r(uint4* r,
    const __half* A, const __half* B,
    int bm, int bn, int K, int k0, int tid)
{
    #pragma unroll
    for (int p = 0; p < 2; p++) {
        int id = p * 256 + tid;
        int row = id >> 2, kc = id & 3;
        r[0+p] = *(const uint4*)&A[(size_t)(bm + row) * K + k0 + kc * 8];
        r[2+p] = *(const uint4*)&B[(size_t)(bn + row) * K + k0 + kc * 8];
    }
}
__device__ __forceinline__ void r2s(__half* sm, const uint4* r, int tid, int st)
{
    #pragma unroll
    for (int p = 0; p < 2; p++) {
        int id = p * 256 + tid;
        int off = (id >> 2) * TSTRIDE + (id & 3) * 8;
        #pragma unroll
        for (int t = 0; t < 2; t++)
            *(uint4*)&sm[(st*2 + t) * (128*TSTRIDE) + off] = r[t*2 + p];
    }
}

template<int EPI>
__global__ void __launch_bounds__(256, 2) gemm_mma(
    const __half* __restrict__ A, const __half* __restrict__ Bm,
    const float* __restrict__ bias, float* __restrict__ C, int M, int N, int K)
{
    extern __shared__ __align__(16) __half sm[];
    const uint32_t sbase = smem_u32(sm);
    const int tid = threadIdx.x;
    const int lane = tid & 31, wid = tid >> 5;
    const int wm = wid & 3, wn = wid >> 2;
    const int bm = blockIdx.y * 128, bn = blockIdx.x * 128;
    const int piece = lane >> 3, pr = lane & 7;

    float acc[2][8][4];
    #pragma unroll
    for (int i = 0; i < 2; i++)
        #pragma unroll
        for (int j = 0; j < 8; j++)
            #pragma unroll
            for (int k = 0; k < 4; k++) acc[i][j][k] = 0.0f;

    const int nit = K >> 5;
    uint4 r[4];
    g2r(r, A, Bm, bm, bn, K, 0, tid);
    r2s(sm, r, tid, 0);
    __syncthreads();

    const int arow = wm*32 + (piece & 1)*8 + pr;
    const int brow = wn*64 + (piece & 1)*8 + pr;
    const int kofp = (piece >> 1) * 8;

    for (int it = 0; it < nit; it++) {
        int st = it & 1;
        bool more = (it + 1) < nit;
        if (more) g2r(r, A, Bm, bm, bn, K, (it + 1) << 5, tid);

        uint32_t tA = sbase + (uint32_t)(st*2) * TILE_B;
        #pragma unroll
        for (int ks = 0; ks < 2; ks++) {
            int koff = ks*16 + kofp;
            uint32_t ah[2][4];
            #pragma unroll
            for (int mt = 0; mt < 2; mt++)
                ldsm4(ah[mt], tA + ((arow + mt*16) * TSTRIDE + koff) * 2);
            #pragma unroll
            for (int np = 0; np < 4; np++) {
                uint32_t b4[4];
                ldsm4(b4, tA + TILE_B + ((brow + np*16) * TSTRIDE + koff) * 2);
                #pragma unroll
                for (int mt = 0; mt < 2; mt++) {
                    mma_fp(acc[mt][np*2],   ah[mt], b4[0], b4[2]);
                    mma_fp(acc[mt][np*2+1], ah[mt], b4[1], b4[3]);
                }
            }
        }
        // Single barrier per iteration (see R9 note).
        if (more) r2s(sm, r, tid, st ^ 1);
        __syncthreads();
    }

    const int cbase = bn + wn * 64;
    if (EPI == 0) {
        #pragma unroll
        for (int mt = 0; mt < 2; mt++)
            #pragma unroll
            for (int half = 0; half < 2; half++) {
                int m = bm + wm*32 + mt*16 + (lane >> 2) + half*8;
                #pragma unroll
                for (int nt = 0; nt < 8; nt++) {
                    int c = cbase + nt*8 + (lane & 3)*2;
                    float2 v;
                    v.x = acc[mt][nt][half*2+0] + bias[c];
                    v.y = acc[mt][nt][half*2+1] + bias[c+1];
                    *(float2*)&C[(size_t)m * N + c] = v;
                }
            }
    } else {
        int which = cbase / DIM;
        int h = (cbase % DIM) >> 6;
        __half* dstp = (which == 0) ? g_qh : (which == 1) ? g_kh : g_vh;
        #pragma unroll
        for (int mt = 0; mt < 2; mt++)
            #pragma unroll
            for (int half = 0; half < 2; half++) {
                int m = bm + wm*32 + mt*16 + (lane >> 2) + half*8;
                int bb = m / NTOK, pos = m - bb * NTOK;
                size_t dof = ((size_t)(bb*HEADS + h) * NTOK + pos) * HD;
                __half* dst = dstp + dof;
                if (which < 2) {
                    const float qs = (which == 0) ? 0.125f : 1.0f;
                    #pragma unroll
                    for (int nt = 0; nt < 4; nt++) {
                        int d0 = nt*8 + (lane & 3)*2;
                        float rl[2], rh[2];
                        #pragma unroll
                        for (int j = 0; j < 2; j++) {
                            float vlo = acc[mt][nt][half*2+j]   + bias[cbase + d0 + j];
                            float vhi = acc[mt][nt+4][half*2+j] + bias[cbase + 32 + d0 + j];
                            float sn = g_sin[pos*32 + d0 + j];
                            float cs = g_cos[pos*32 + d0 + j];
                            rl[j] = (vlo*cs - vhi*sn) * qs;
                            rh[j] = (vhi*cs + vlo*sn) * qs;
                        }
                        *(__half2*)&dst[d0]      = __floats2half2_rn(rl[0], rl[1]);
                        *(__half2*)&dst[32 + d0] = __floats2half2_rn(rh[0], rh[1]);
                    }
                } else {
                    #pragma unroll
                    for (int nt = 0; nt < 8; nt++) {
                        int d = nt*8 + (lane & 3)*2;
                        float v0 = acc[mt][nt][half*2+0] + bias[cbase + d];
                        float v1 = acc[mt][nt][half*2+1] + bias[cbase + d + 1];
                        *(__half2*)&dst[d] = __floats2half2_rn(v0, v1);
                    }
                }
            }
    }
}

// ==== attention: HMMA flash, warp = 32 q-rows x 64 keys, 2-stage K/V ====
// CTA = 256 q-rows (8 warps). Each K/V fragment load feeds 2 MMA blocks.
#define AST 72
#define STAGEH (2*64*AST)            // halves per stage (K tile + V tile)
#define ATTN_SMEM (2*STAGEH*2)       // 36864 bytes

__device__ __forceinline__ void g2r_attn(uint4* rv,
    const __half* Kh, const __half* Vh, int k0, int tid)
{
    #pragma unroll
    for (int i = 0; i < 4; i++) {
        int lin = i * 256 + tid;
        int arr = lin >> 9, rem = lin & 511;
        int row = rem >> 3, c = (rem & 7) * 8;
        const __half* src = (arr == 0 ? Kh : Vh) + (size_t)(k0 + row) * HD + c;
        rv[i] = *(const uint4*)src;
    }
}
__device__ __forceinline__ void r2s_attn(__half* smh, const uint4* rv,
                                         int st, int tid)
{
    __half* base = smh + st * STAGEH;
    #pragma unroll
    for (int i = 0; i < 4; i++) {
        int lin = i * 256 + tid;
        int arr = lin >> 9, rem = lin & 511;
        int row = rem >> 3, c = (rem & 7) * 8;
        *(uint4*)&base[arr * (64*AST) + row * AST + c] = rv[i];
    }
}

__global__ void __launch_bounds__(256, 1) attn_mma()
{
    extern __shared__ __align__(16) __half smh[];
    const uint32_t sb = smem_u32(smh);

    const int tid = threadIdx.x;
    const int lane = tid & 31, w = tid >> 5;
    const int l15 = lane & 15, l16 = lane >> 4;
    const int bh = blockIdx.y, q0 = blockIdx.x * 256;

    const __half* Qh = g_qh + ((size_t)bh * NTOK + q0) * HD;
    const __half* Kh = g_kh + (size_t)bh * NTOK * HD;
    const __half* Vh = g_vh + (size_t)bh * NTOK * HD;

    // ---- stage Q (256 rows fill the whole smem buffer), extract frags ----
    #pragma unroll
    for (int t = 0; t < 8; t++) {
        int lin = t * 256 + tid;
        int row = lin >> 3, c = (lin & 7) * 8;
        *(uint4*)&smh[row * AST + c] = *(const uint4*)&Qh[(size_t)row * HD + c];
    }
    __syncthreads();
    uint32_t qf[2][4][4];
    #pragma unroll
    for (int b = 0; b < 2; b++) {
        uint32_t qa = sb + (((w*32 + b*16 + l15) * AST) + l16*8) * 2;
        #pragma unroll
        for (int ks = 0; ks < 4; ks++)
            ldsm4(qf[b][ks], qa + ks*32);
    }

    // ---- pipeline prologue ----
    uint4 rv[4];
    g2r_attn(rv, Kh, Vh, 0, tid);
    __syncthreads();                 // qf extraction done before overwrite
    r2s_attn(smh, rv, 0, tid);
    g2r_attn(rv, Kh, Vh, 64, tid);   // prefetch tile 1
    __syncthreads();

    float acc[2][8][4];
    #pragma unroll
    for (int b = 0; b < 2; b++)
        #pragma unroll
        for (int i = 0; i < 8; i++)
            #pragma unroll
            for (int j = 0; j < 4; j++) acc[b][i][j] = 0.0f;
    float mrow[2][2], lrow[2][2];
    #pragma unroll
    for (int b = 0; b < 2; b++) {
        mrow[b][0] = -1e30f; mrow[b][1] = -1e30f;
        lrow[b][0] = 0.0f;   lrow[b][1] = 0.0f;
    }

    const uint32_t lko = (l15 * AST + l16*8) * 2;
    const int NT = NTOK / 64;        // 36

    for (int t = 0; t < NT; t++) {
        if (t + 1 < NT) r2s_attn(smh, rv, (t + 1) & 1, tid);
        if (t + 2 < NT) g2r_attn(rv, Kh, Vh, (t + 2) * 64, tid);

        uint32_t stg = sb + (uint32_t)(t & 1) * (STAGEH * 2);
        uint32_t kbase = stg + lko;
        uint32_t vbase = stg + 64*AST*2 + lko;

        // ---- S = Q K^T (each K fragment feeds both q-blocks) ----
        float s[2][8][4];
        #pragma unroll
        for (int b = 0; b < 2; b++)
            #pragma unroll
            for (int i = 0; i < 8; i++)
                #pragma unroll
                for (int j = 0; j < 4; j++) s[b][i][j] = 0.0f;
        #pragma unroll
        for (int ks = 0; ks < 4; ks++) {
            #pragma unroll
            for (int nbp = 0; nbp < 8; nbp += 2) {
                uint32_t kh4[4];
                ldsm4(kh4, kbase + (nbp*8*AST + ks*16) * 2);
                #pragma unroll
                for (int b = 0; b < 2; b++) {
                    mma_fp(s[b][nbp],   qf[b][ks], kh4[0], kh4[2]);
                    mma_fp(s[b][nbp+1], qf[b][ks], kh4[1], kh4[3]);
                }
            }
        }

        // ---- online softmax + P conversion (per q-block) ----
        uint32_t ap[2][4][4];
        #pragma unroll
        for (int b = 0; b < 2; b++) {
            float mx0 = -1e30f, mx1 = -1e30f;
            #pragma unroll
            for (int i = 0; i < 8; i++) {
                mx0 = fmaxf(mx0, fmaxf(s[b][i][0], s[b][i][1]));
                mx1 = fmaxf(mx1, fmaxf(s[b][i][2], s[b][i][3]));
            }
            mx0 = fmaxf(mx0, __shfl_xor_sync(0xffffffffu, mx0, 1));
            mx0 = fmaxf(mx0, __shfl_xor_sync(0xffffffffu, mx0, 2));
            mx1 = fmaxf(mx1, __shfl_xor_sync(0xffffffffu, mx1, 1));
            mx1 = fmaxf(mx1, __shfl_xor_sync(0xffffffffu, mx1, 2));
            float nm0 = fmaxf(mrow[b][0], mx0), nm1 = fmaxf(mrow[b][1], mx1);
            float f0 = fast_exp(mrow[b][0] - nm0), f1 = fast_exp(mrow[b][1] - nm1);
            mrow[b][0] = nm0; mrow[b][1] = nm1;
            float sum0 = 0.0f, sum1 = 0.0f;
            #pragma unroll
            for (int i = 0; i < 8; i++) {
                s[b][i][0] = fast_exp(s[b][i][0] - nm0); sum0 += s[b][i][0];
                s[b][i][1] = fast_exp(s[b][i][1] - nm0); sum0 += s[b][i][1];
                s[b][i][2] = fast_exp(s[b][i][2] - nm1); sum1 += s[b][i][2];
                s[b][i][3] = fast_exp(s[b][i][3] - nm1); sum1 += s[b][i][3];
            }
            sum0 += __shfl_xor_sync(0xffffffffu, sum0, 1);
            sum0 += __shfl_xor_sync(0xffffffffu, sum0, 2);
            sum1 += __shfl_xor_sync(0xffffffffu, sum1, 1);
            sum1 += __shfl_xor_sync(0xffffffffu, sum1, 2);
            lrow[b][0] = lrow[b][0] * f0 + sum0;
            lrow[b][1] = lrow[b][1] * f1 + sum1;
            #pragma unroll
            for (int i = 0; i < 8; i++) {
                acc[b][i][0] *= f0; acc[b][i][1] *= f0;
                acc[b][i][2] *= f1; acc[b][i][3] *= f1;
            }
            #pragma unroll
            for (int ks = 0; ks < 4; ks++) {
                int n0 = 2*ks, n1 = 2*ks + 1;
                __half2 h0 = __floats2half2_rn(s[b][n0][0], s[b][n0][1]);
                __half2 h1 = __floats2half2_rn(s[b][n0][2], s[b][n0][3]);
                __half2 h2 = __floats2half2_rn(s[b][n1][0], s[b][n1][1]);
                __half2 h3 = __floats2half2_rn(s[b][n1][2], s[b][n1][3]);
                ap[b][ks][0] = *(uint32_t*)&h0;
                ap[b][ks][1] = *(uint32_t*)&h1;
                ap[b][ks][2] = *(uint32_t*)&h2;
                ap[b][ks][3] = *(uint32_t*)&h3;
            }
        }

        // ---- O += P V (each V fragment feeds both q-blocks) ----
        #pragma unroll
        for (int ks = 0; ks < 4; ks++) {
            #pragma unroll
            for (int nbp = 0; nbp < 8; nbp += 2) {
                uint32_t vh4[4];
                ldsm4t(vh4, vbase + (ks*16*AST + nbp*8) * 2);
                #pragma unroll
                for (int b = 0; b < 2; b++) {
                    mma_fp(acc[b][nbp],   ap[b][ks], vh4[0], vh4[1]);
                    mma_fp(acc[b][nbp+1], ap[b][ks], vh4[2], vh4[3]);
                }
            }
        }

        __syncthreads();  // single barrier per iteration (see R14 note)
    }

    // ---- normalize + write O as fp16, [b, n, h*64 + d] ----
    int bb = bh / HEADS, h = bh - bb * HEADS;
    int col = h*HD + (lane & 3)*2;
    #pragma unroll
    for (int b = 0; b < 2; b++) {
        float inv0 = 1.0f / lrow[b][0], inv1 = 1.0f / lrow[b][1];
        int r0 = q0 + w*32 + b*16 + (lane >> 2);
        #pragma unroll
        for (int nb = 0; nb < 8; nb++) {
            size_t o0 = ((size_t)(bb*NTOK + r0))     * DIM + col + nb*8;
            size_t o1 = ((size_t)(bb*NTOK + r0 + 8)) * DIM + col + nb*8;
            *(__half2*)&g_o16[o0] =
                __floats2half2_rn(acc[b][nb][0]*inv0, acc[b][nb][1]*inv0);
            *(__half2*)&g_o16[o1] =
                __floats2half2_rn(acc[b][nb][2]*inv1, acc[b][nb][3]*inv1);
        }
    }
}

// ==================== launcher ====================
extern "C" void kernel_launch(void* const* d_in, const int* in_sizes, int n_in,
                              void* d_out, int out_size)
{
    const float* x      = (const float*)d_in[0];
    const float* w_qkv  = (const float*)d_in[1];
    const float* b_qkv  = (const float*)d_in[2];
    const float* w_proj = (const float*)d_in[3];
    const float* b_proj = (const float*)d_in[4];
    float* out = (float*)d_out;

    void *xp, *wq, *wp, *op;
    cudaGetSymbolAddress(&xp, g_x16);
    cudaGetSymbolAddress(&wq, g_wq16);
    cudaGetSymbolAddress(&wp, g_wp16);
    cudaGetSymbolAddress(&op, g_o16);

    cudaFuncSetAttribute(gemm_mma<0>, cudaFuncAttributeMaxDynamicSharedMemorySize,
                         GEMM_SMEM_B);
    cudaFuncSetAttribute(gemm_mma<1>, cudaFuncAttributeMaxDynamicSharedMemorySize,
                         GEMM_SMEM_B);
    cudaFuncSetAttribute(attn_mma, cudaFuncAttributeMaxDynamicSharedMemorySize,
                         ATTN_SMEM);

    // 0) fused prep: x/w_qkv/w_proj fp32->fp16 + rope table (one launch)
    prep_kernel<<<(PREP_TOTAL + 255)/256, 256>>>(x, w_qkv, w_proj);

    // 1) QKV GEMM + bias + RoPE + fp16 scatter
    gemm_mma<1><<<dim3(3*DIM/128, MROWS/128), 256, GEMM_SMEM_B>>>(
        (const __half*)xp, (const __half*)wq, b_qkv, nullptr, MROWS, 3*DIM, DIM);

    // 2) attention (HMMA flash, warp = 32 q-rows x 64 keys)
    attn_mma<<<dim3(NTOK/256, BHC), 256, ATTN_SMEM>>>();

    // 3) output projection -> d_out
    gemm_mma<0><<<dim3(DIM/128, MROWS/128), 256, GEMM_SMEM_B>>>(
        (const __half*)op, (const __half*)wp, b_proj, out, MROWS, DIM, DIM);
}